// round 1
// baseline (speedup 1.0000x reference)
#include <cuda_runtime.h>
#include <math.h>

static constexpr int NTOK = 2048;
static constexpr int DIM  = 512;
static constexpr int NH   = 8;

// ---------------- scratch (allocation-free: __device__ globals) ----------------
__device__ float g_qm[(size_t)NH * NTOK * DIM];
__device__ float g_ki[(size_t)NH * NTOK * DIM];
__device__ float g_vi[(size_t)NH * NTOK * DIM];
__device__ float g_qi[(size_t)NH * NTOK * DIM];
__device__ float g_km[(size_t)NH * NTOK * DIM];
__device__ float g_vm[(size_t)NH * NTOK * DIM];
__device__ float g_si[(size_t)NH * NTOK * NTOK];   // scores, image-kv direction
__device__ float g_sm[(size_t)NH * NTOK * NTOK];   // scores, metadata-kv direction
__device__ float g_ci[(size_t)NTOK * NH * DIM];    // concat(res_i) [N, H*512]
__device__ float g_cm[(size_t)NTOK * NH * DIM];    // concat(res_m) [N, H*512]

// ---------------------------------------------------------------------------
// GEMM NT:  C[m,n] = sum_k A[m,k] * B[n,k]  (+ bias[n]) (+ resid[m,n])
// Tiles: 128x128x8, 256 threads, 8x8 per-thread micro-tile.
// All problem dims are multiples of the tile sizes -> no bounds checks.
// blockIdx.z batches over heads via element strides sA/sB/sC/sBias.
// ---------------------------------------------------------------------------
__global__ __launch_bounds__(256, 2) void gemm_nt_k(
    const float* __restrict__ A, const float* __restrict__ B,
    float* __restrict__ C,
    const float* __restrict__ bias, const float* __restrict__ resid,
    int M, int Nc, int K, int lda, int ldb, int ldc, int ldr,
    size_t sA, size_t sB, size_t sC, size_t sBias)
{
    const int z = blockIdx.z;
    A += (size_t)z * sA;
    B += (size_t)z * sB;
    C += (size_t)z * sC;
    if (bias) bias += (size_t)z * sBias;

    __shared__ float As[8][128];
    __shared__ float Bs[8][128];

    const int m0 = blockIdx.y * 128;
    const int n0 = blockIdx.x * 128;
    const int tid = threadIdx.x;
    const int tx = tid & 15;         // 16 cols of threads
    const int ty = tid >> 4;         // 16 rows of threads
    const int lrow = tid >> 1;       // 0..127
    const int lk   = (tid & 1) * 4;  // 0 or 4

    float acc[8][8];
#pragma unroll
    for (int i = 0; i < 8; i++)
#pragma unroll
        for (int j = 0; j < 8; j++) acc[i][j] = 0.0f;

    const float* Ap = A + (size_t)(m0 + lrow) * lda + lk;
    const float* Bp = B + (size_t)(n0 + lrow) * ldb + lk;

    for (int k0 = 0; k0 < K; k0 += 8) {
        float4 a4 = *(const float4*)(Ap + k0);
        float4 b4 = *(const float4*)(Bp + k0);
        As[lk + 0][lrow] = a4.x; As[lk + 1][lrow] = a4.y;
        As[lk + 2][lrow] = a4.z; As[lk + 3][lrow] = a4.w;
        Bs[lk + 0][lrow] = b4.x; Bs[lk + 1][lrow] = b4.y;
        Bs[lk + 2][lrow] = b4.z; Bs[lk + 3][lrow] = b4.w;
        __syncthreads();
#pragma unroll
        for (int k = 0; k < 8; k++) {
            float4 a0 = *(const float4*)&As[k][ty * 8];
            float4 a1 = *(const float4*)&As[k][ty * 8 + 4];
            float4 b0 = *(const float4*)&Bs[k][tx * 8];
            float4 b1 = *(const float4*)&Bs[k][tx * 8 + 4];
            float af[8] = {a0.x, a0.y, a0.z, a0.w, a1.x, a1.y, a1.z, a1.w};
            float bf[8] = {b0.x, b0.y, b0.z, b0.w, b1.x, b1.y, b1.z, b1.w};
#pragma unroll
            for (int i = 0; i < 8; i++)
#pragma unroll
                for (int j = 0; j < 8; j++)
                    acc[i][j] = fmaf(af[i], bf[j], acc[i][j]);
        }
        __syncthreads();
    }

#pragma unroll
    for (int i = 0; i < 8; i++) {
        const int m = m0 + ty * 8 + i;
#pragma unroll
        for (int j = 0; j < 8; j++) {
            const int n = n0 + tx * 8 + j;
            float v = acc[i][j];
            if (bias)  v += bias[n];
            if (resid) v += resid[(size_t)m * ldr + n];
            C[(size_t)m * ldc + n] = v;
        }
    }
}

// ---------------------------------------------------------------------------
// GEMM NN:  C[m,n] = sum_k A[m,k] * B[k,n]   (used for P @ V)
// ---------------------------------------------------------------------------
__global__ __launch_bounds__(256, 2) void gemm_nn_k(
    const float* __restrict__ A, const float* __restrict__ B,
    float* __restrict__ C,
    int M, int Nc, int K, int lda, int ldb, int ldc,
    size_t sA, size_t sB, size_t sC)
{
    const int z = blockIdx.z;
    A += (size_t)z * sA;
    B += (size_t)z * sB;
    C += (size_t)z * sC;

    __shared__ float As[8][128];
    __shared__ float Bs[8][128];

    const int m0 = blockIdx.y * 128;
    const int n0 = blockIdx.x * 128;
    const int tid = threadIdx.x;
    const int tx = tid & 15;
    const int ty = tid >> 4;
    const int lrow = tid >> 1;
    const int lk   = (tid & 1) * 4;
    const int brow = tid >> 5;        // 0..7
    const int bcol = (tid & 31) * 4;  // 0..124

    float acc[8][8];
#pragma unroll
    for (int i = 0; i < 8; i++)
#pragma unroll
        for (int j = 0; j < 8; j++) acc[i][j] = 0.0f;

    const float* Ap = A + (size_t)(m0 + lrow) * lda + lk;

    for (int k0 = 0; k0 < K; k0 += 8) {
        float4 a4 = *(const float4*)(Ap + k0);
        float4 b4 = *(const float4*)(B + (size_t)(k0 + brow) * ldb + n0 + bcol);
        As[lk + 0][lrow] = a4.x; As[lk + 1][lrow] = a4.y;
        As[lk + 2][lrow] = a4.z; As[lk + 3][lrow] = a4.w;
        *(float4*)&Bs[brow][bcol] = b4;
        __syncthreads();
#pragma unroll
        for (int k = 0; k < 8; k++) {
            float4 a0 = *(const float4*)&As[k][ty * 8];
            float4 a1 = *(const float4*)&As[k][ty * 8 + 4];
            float4 b0 = *(const float4*)&Bs[k][tx * 8];
            float4 b1 = *(const float4*)&Bs[k][tx * 8 + 4];
            float af[8] = {a0.x, a0.y, a0.z, a0.w, a1.x, a1.y, a1.z, a1.w};
            float bf[8] = {b0.x, b0.y, b0.z, b0.w, b1.x, b1.y, b1.z, b1.w};
#pragma unroll
            for (int i = 0; i < 8; i++)
#pragma unroll
                for (int j = 0; j < 8; j++)
                    acc[i][j] = fmaf(af[i], bf[j], acc[i][j]);
        }
        __syncthreads();
    }

#pragma unroll
    for (int i = 0; i < 8; i++) {
        const int m = m0 + ty * 8 + i;
#pragma unroll
        for (int j = 0; j < 8; j++) {
            const int n = n0 + tx * 8 + j;
            C[(size_t)m * ldc + n] = acc[i][j];
        }
    }
}

// ---------------------------------------------------------------------------
// Row softmax over rows of length NTOK (one block per row), with pre-scale.
// ---------------------------------------------------------------------------
__global__ __launch_bounds__(256) void softmax_k(float* __restrict__ S, float scale)
{
    float* row = S + (size_t)blockIdx.x * NTOK;
    const int tid = threadIdx.x;

    float v[8];
    float mx = -1e30f;
#pragma unroll
    for (int i = 0; i < 8; i++) {
        v[i] = row[tid + i * 256] * scale;
        mx = fmaxf(mx, v[i]);
    }

    __shared__ float red[8];
#pragma unroll
    for (int o = 16; o; o >>= 1) mx = fmaxf(mx, __shfl_xor_sync(0xffffffffu, mx, o));
    if ((tid & 31) == 0) red[tid >> 5] = mx;
    __syncthreads();
    mx = red[0];
#pragma unroll
    for (int i = 1; i < 8; i++) mx = fmaxf(mx, red[i]);

    float sum = 0.0f;
#pragma unroll
    for (int i = 0; i < 8; i++) {
        v[i] = __expf(v[i] - mx);
        sum += v[i];
    }
    __syncthreads();  // red reuse
#pragma unroll
    for (int o = 16; o; o >>= 1) sum += __shfl_xor_sync(0xffffffffu, sum, o);
    if ((tid & 31) == 0) red[tid >> 5] = sum;
    __syncthreads();
    sum = red[0];
#pragma unroll
    for (int i = 1; i < 8; i++) sum += red[i];

    const float inv = 1.0f / sum;
#pragma unroll
    for (int i = 0; i < 8; i++) row[tid + i * 256] = v[i] * inv;
}

// ---------------------------------------------------------------------------
extern "C" void kernel_launch(void* const* d_in, const int* in_sizes, int n_in,
                              void* d_out, int out_size)
{
    (void)in_sizes; (void)n_in; (void)out_size;

    const float* image = (const float*)d_in[0];
    const float* meta  = (const float*)d_in[1];
    const float* Wq_m  = (const float*)d_in[2];  const float* bq_m = (const float*)d_in[3];
    const float* Wk_i  = (const float*)d_in[4];  const float* bk_i = (const float*)d_in[5];
    const float* Wv_i  = (const float*)d_in[6];  const float* bv_i = (const float*)d_in[7];
    const float* Wq_i  = (const float*)d_in[8];  const float* bq_i = (const float*)d_in[9];
    const float* Wk_m  = (const float*)d_in[10]; const float* bk_m = (const float*)d_in[11];
    const float* Wv_m  = (const float*)d_in[12]; const float* bv_m = (const float*)d_in[13];
    const float* Wli   = (const float*)d_in[14]; const float* bli  = (const float*)d_in[15];
    const float* Wlm   = (const float*)d_in[16]; const float* blm  = (const float*)d_in[17];
    float* out = (float*)d_out;

    float *qm, *ki, *vi, *qi, *km, *vm, *si, *sm, *ci, *cm;
    cudaGetSymbolAddress((void**)&qm, g_qm);
    cudaGetSymbolAddress((void**)&ki, g_ki);
    cudaGetSymbolAddress((void**)&vi, g_vi);
    cudaGetSymbolAddress((void**)&qi, g_qi);
    cudaGetSymbolAddress((void**)&km, g_km);
    cudaGetSymbolAddress((void**)&vm, g_vm);
    cudaGetSymbolAddress((void**)&si, g_si);
    cudaGetSymbolAddress((void**)&sm, g_sm);
    cudaGetSymbolAddress((void**)&ci, g_ci);
    cudaGetSymbolAddress((void**)&cm, g_cm);

    const dim3 blk(256);

    // ---- projections: X[N,512] @ W[h]^T + b[h] -> [H,N,512], batched over z=h
    const dim3 gproj(DIM / 128, NTOK / 128, NH);
    const size_t sW = (size_t)DIM * DIM, sO = (size_t)NTOK * DIM, sBq = DIM;
    gemm_nt_k<<<gproj, blk>>>(meta,  Wq_m, qm, bq_m, nullptr, NTOK, DIM, DIM, DIM, DIM, DIM, 0, 0, sW, sO, sBq);
    gemm_nt_k<<<gproj, blk>>>(image, Wk_i, ki, bk_i, nullptr, NTOK, DIM, DIM, DIM, DIM, DIM, 0, 0, sW, sO, sBq);
    gemm_nt_k<<<gproj, blk>>>(image, Wv_i, vi, bv_i, nullptr, NTOK, DIM, DIM, DIM, DIM, DIM, 0, 0, sW, sO, sBq);
    gemm_nt_k<<<gproj, blk>>>(image, Wq_i, qi, bq_i, nullptr, NTOK, DIM, DIM, DIM, DIM, DIM, 0, 0, sW, sO, sBq);
    gemm_nt_k<<<gproj, blk>>>(meta,  Wk_m, km, bk_m, nullptr, NTOK, DIM, DIM, DIM, DIM, DIM, 0, 0, sW, sO, sBq);
    gemm_nt_k<<<gproj, blk>>>(meta,  Wv_m, vm, bv_m, nullptr, NTOK, DIM, DIM, DIM, DIM, DIM, 0, 0, sW, sO, sBq);

    // ---- scores: Q[h] @ K[h]^T -> [H,N,N]
    const dim3 gsc(NTOK / 128, NTOK / 128, NH);
    const size_t sS = (size_t)NTOK * NTOK;
    gemm_nt_k<<<gsc, blk>>>(qm, ki, si, nullptr, nullptr, NTOK, NTOK, DIM, DIM, DIM, NTOK, 0, sO, sO, sS, 0);
    gemm_nt_k<<<gsc, blk>>>(qi, km, sm, nullptr, nullptr, NTOK, NTOK, DIM, DIM, DIM, NTOK, 0, sO, sO, sS, 0);

    // ---- softmax rows (scale = 1/sqrt(512))
    const float scale = 0.04419417382415922f;
    softmax_k<<<NH * NTOK, 256>>>(si, scale);
    softmax_k<<<NH * NTOK, 256>>>(sm, scale);

    // ---- AV: P[h] @ V[h] -> concat layout [N, H*512] (column offset h*512)
    const dim3 gav(DIM / 128, NTOK / 128, NH);
    gemm_nn_k<<<gav, blk>>>(si, vi, ci, NTOK, DIM, NTOK, NTOK, DIM, NH * DIM, sS, sO, (size_t)DIM);
    gemm_nn_k<<<gav, blk>>>(sm, vm, cm, NTOK, DIM, NTOK, NTOK, DIM, NH * DIM, sS, sO, (size_t)DIM);

    // ---- final linears + bias + residual, write into d_out [N, 1024]
    const dim3 gfin(DIM / 128, NTOK / 128, 1);
    gemm_nt_k<<<gfin, blk>>>(ci, Wli, out,        bli, image, NTOK, DIM, NH * DIM, NH * DIM, NH * DIM, 2 * DIM, DIM, 0, 0, 0, 0);
    gemm_nt_k<<<gfin, blk>>>(cm, Wlm, out + DIM,  blm, meta,  NTOK, DIM, NH * DIM, NH * DIM, NH * DIM, 2 * DIM, DIM, 0, 0, 0, 0);
}

// round 3
// speedup vs baseline: 2.1868x; 2.1868x over previous
#include <cuda_runtime.h>
#include <cstdint>

static constexpr int NTOK = 2048;
static constexpr int DIM  = 512;
static constexpr int NH   = 8;

// ---------------- scratch (allocation-free: __device__ globals) ----------------
__device__ float g_qm[(size_t)NH * NTOK * DIM];
__device__ float g_ki[(size_t)NH * NTOK * DIM];
__device__ float g_vi[(size_t)NH * NTOK * DIM];
__device__ float g_qi[(size_t)NH * NTOK * DIM];
__device__ float g_km[(size_t)NH * NTOK * DIM];
__device__ float g_vm[(size_t)NH * NTOK * DIM];
__device__ float g_si[(size_t)NH * NTOK * NTOK];
__device__ float g_sm[(size_t)NH * NTOK * NTOK];
__device__ float g_ci[(size_t)NTOK * NH * DIM];
__device__ float g_cm[(size_t)NTOK * NH * DIM];

#define DEVINL __device__ __forceinline__

DEVINL float tf32r(float x) { float y; asm("cvt.rna.tf32.f32 %0, %1;" : "=f"(y) : "f"(x)); return y; }

DEVINL void mma8(float* c, const uint32_t* a, const uint32_t* b) {
    asm volatile("mma.sync.aligned.m16n8k8.row.col.f32.tf32.tf32.f32 "
        "{%0,%1,%2,%3}, {%4,%5,%6,%7}, {%8,%9}, {%0,%1,%2,%3};"
        : "+f"(c[0]), "+f"(c[1]), "+f"(c[2]), "+f"(c[3])
        : "r"(a[0]), "r"(a[1]), "r"(a[2]), "r"(a[3]), "r"(b[0]), "r"(b[1]));
}

// Smem tile layout: [row][20] floats (pad 20 -> conflict-free fragment loads:
// banks (20*m + k) % 32 cover all 32 for m in 0..7, k in 0..3 pattern).
static constexpr int KP = 20;      // padded row length (16 k + 4 pad)
static constexpr int KC = 16;      // K chunk

union SmemU {
    float tiles[2][2][128 * KP];   // [buf][A=0/B=1][row*KP + k]   40960 B
    float stage[64 * 132];         // epilogue staging              33792 B
};

// ---------------------------------------------------------------------------
// tf32 mma.sync GEMM:
//   C[m,n] = sum_k A[m,k] * Bsrc(n,k)  (+ bias[n]) (+ resid[m,n])
//   bTransB==0: Bsrc(n,k) = B[n*ldb + k]   (NT: B row-major [n][k])
//   bTransB==1: Bsrc(n,k) = B[k*ldb + n]   (NN: B row-major [k][n])
// CTA tile 128x128, 256 threads, warp tile 64x32, K chunk 16, double buffered.
// ---------------------------------------------------------------------------
__global__ __launch_bounds__(256) void gemm_mma(
    const float* __restrict__ A, const float* __restrict__ B, float* __restrict__ C,
    const float* __restrict__ bias, const float* __restrict__ resid,
    int K, int lda, int ldb, int ldc, int ldr, int bTransB,
    size_t strA, size_t strB, size_t strC, size_t strBias)
{
    __shared__ SmemU su;

    const int tid  = threadIdx.x;
    const int warp = tid >> 5;
    const int lane = tid & 31;
    const int wm   = warp & 1;       // 2 warps along m
    const int wn   = warp >> 1;      // 4 warps along n
    const int gid  = lane >> 2;      // groupID 0..7
    const int tig  = lane & 3;       // thread-in-group 0..3

    const int z = blockIdx.z;
    A += (size_t)z * strA;
    B += (size_t)z * strB;
    C += (size_t)z * strC;
    if (bias) bias += (size_t)z * strBias;

    const int m0 = blockIdx.y * 128;
    const int n0 = blockIdx.x * 128;

    // NT fill mapping: thread -> (row 0..127, k-offset 0/4), 2 float4 each
    const int frow = tid >> 1;
    const int fk4  = (tid & 1) * 4;
    // NN fill mapping (B only): thread -> (k-row 0..15, n-seg), 2 float4 each
    const int gkrow = tid & 15;
    const int gnseg = tid >> 4;      // 0..15 ; segs gnseg and gnseg+16

    float acc[4][4][4];
#pragma unroll
    for (int i = 0; i < 4; i++)
#pragma unroll
        for (int j = 0; j < 4; j++)
#pragma unroll
            for (int r = 0; r < 4; r++) acc[i][j][r] = 0.0f;

    const int NC = K / KC;
    float4 ra0, ra1, rb0, rb1;

    // ---- load chunk c into registers ----
    auto load_regs = [&](int c) {
        const int k0 = c * KC;
        ra0 = *(const float4*)(A + (size_t)(m0 + frow) * lda + k0 + fk4);
        ra1 = *(const float4*)(A + (size_t)(m0 + frow) * lda + k0 + fk4 + 8);
        if (!bTransB) {
            rb0 = *(const float4*)(B + (size_t)(n0 + frow) * ldb + k0 + fk4);
            rb1 = *(const float4*)(B + (size_t)(n0 + frow) * ldb + k0 + fk4 + 8);
        } else {
            rb0 = *(const float4*)(B + (size_t)(k0 + gkrow) * ldb + n0 + gnseg * 4);
            rb1 = *(const float4*)(B + (size_t)(k0 + gkrow) * ldb + n0 + (gnseg + 16) * 4);
        }
    };

    // ---- cvt to tf32 + store registers into smem buffer b ----
    auto store_smem = [&](int b) {
        float4 a0 = ra0, a1 = ra1;
        a0.x = tf32r(a0.x); a0.y = tf32r(a0.y); a0.z = tf32r(a0.z); a0.w = tf32r(a0.w);
        a1.x = tf32r(a1.x); a1.y = tf32r(a1.y); a1.z = tf32r(a1.z); a1.w = tf32r(a1.w);
        *(float4*)&su.tiles[b][0][frow * KP + fk4]     = a0;
        *(float4*)&su.tiles[b][0][frow * KP + fk4 + 8] = a1;
        float4 b0 = rb0, b1 = rb1;
        b0.x = tf32r(b0.x); b0.y = tf32r(b0.y); b0.z = tf32r(b0.z); b0.w = tf32r(b0.w);
        b1.x = tf32r(b1.x); b1.y = tf32r(b1.y); b1.z = tf32r(b1.z); b1.w = tf32r(b1.w);
        if (!bTransB) {
            *(float4*)&su.tiles[b][1][frow * KP + fk4]     = b0;
            *(float4*)&su.tiles[b][1][frow * KP + fk4 + 8] = b1;
        } else {
            float bv0[4] = {b0.x, b0.y, b0.z, b0.w};
            float bv1[4] = {b1.x, b1.y, b1.z, b1.w};
#pragma unroll
            for (int j = 0; j < 4; j++) {
                su.tiles[b][1][(gnseg * 4 + j) * KP + gkrow]        = bv0[j];
                su.tiles[b][1][((gnseg + 16) * 4 + j) * KP + gkrow] = bv1[j];
            }
        }
    };

    load_regs(0);
    store_smem(0);
    __syncthreads();

    for (int c = 0; c < NC; c++) {
        const int buf = c & 1;
        if (c + 1 < NC) load_regs(c + 1);

        const float* As = su.tiles[buf][0];
        const float* Bs = su.tiles[buf][1];
#pragma unroll
        for (int ks = 0; ks < KC; ks += 8) {
            uint32_t af[4][4], bf[4][2];
#pragma unroll
            for (int mt = 0; mt < 4; mt++) {
                const int m = wm * 64 + mt * 16 + gid;
                const int k = ks + tig;
                af[mt][0] = __float_as_uint(As[m * KP + k]);
                af[mt][1] = __float_as_uint(As[(m + 8) * KP + k]);
                af[mt][2] = __float_as_uint(As[m * KP + k + 4]);
                af[mt][3] = __float_as_uint(As[(m + 8) * KP + k + 4]);
            }
#pragma unroll
            for (int nt = 0; nt < 4; nt++) {
                const int n = wn * 32 + nt * 8 + gid;
                const int k = ks + tig;
                bf[nt][0] = __float_as_uint(Bs[n * KP + k]);
                bf[nt][1] = __float_as_uint(Bs[n * KP + k + 4]);
            }
#pragma unroll
            for (int mt = 0; mt < 4; mt++)
#pragma unroll
                for (int nt = 0; nt < 4; nt++)
                    mma8(acc[mt][nt], af[mt], bf[nt]);
        }

        if (c + 1 < NC) {
            store_smem((c + 1) & 1);
        }
        __syncthreads();
    }

    // -------- epilogue: stage 64 rows at a time through smem --------
    for (int p = 0; p < 2; p++) {
        if (wm == p) {
#pragma unroll
            for (int mt = 0; mt < 4; mt++) {
                const int lr = mt * 16 + gid;
#pragma unroll
                for (int nt = 0; nt < 4; nt++) {
                    const int col = wn * 32 + nt * 8 + 2 * tig;
                    *(float2*)&su.stage[lr * 132 + col]       = make_float2(acc[mt][nt][0], acc[mt][nt][1]);
                    *(float2*)&su.stage[(lr + 8) * 132 + col] = make_float2(acc[mt][nt][2], acc[mt][nt][3]);
                }
            }
        }
        __syncthreads();
#pragma unroll
        for (int i = 0; i < 8; i++) {
            const int idx = tid + i * 256;       // 0..2047
            const int row = idx >> 5;            // 0..63
            const int c4  = (idx & 31) * 4;      // 0..124
            float4 v = *(float4*)&su.stage[row * 132 + c4];
            const int n = n0 + c4;
            if (bias) {
                v.x += bias[n + 0]; v.y += bias[n + 1];
                v.z += bias[n + 2]; v.w += bias[n + 3];
            }
            const int m = m0 + p * 64 + row;
            if (resid) {
                float4 rr = *(const float4*)(resid + (size_t)m * ldr + n);
                v.x += rr.x; v.y += rr.y; v.z += rr.z; v.w += rr.w;
            }
            *(float4*)(C + (size_t)m * ldc + n) = v;
        }
        __syncthreads();
    }
}

// ---------------------------------------------------------------------------
// Row softmax over rows of length NTOK (one block per row), with pre-scale.
// ---------------------------------------------------------------------------
__global__ __launch_bounds__(256) void softmax_k(float* __restrict__ S, float scale)
{
    float* row = S + (size_t)blockIdx.x * NTOK;
    const int tid = threadIdx.x;

    float v[8];
    float mx = -1e30f;
#pragma unroll
    for (int i = 0; i < 8; i++) {
        v[i] = row[tid + i * 256] * scale;
        mx = fmaxf(mx, v[i]);
    }

    __shared__ float red[8];
#pragma unroll
    for (int o = 16; o; o >>= 1) mx = fmaxf(mx, __shfl_xor_sync(0xffffffffu, mx, o));
    if ((tid & 31) == 0) red[tid >> 5] = mx;
    __syncthreads();
    mx = red[0];
#pragma unroll
    for (int i = 1; i < 8; i++) mx = fmaxf(mx, red[i]);

    float sum = 0.0f;
#pragma unroll
    for (int i = 0; i < 8; i++) {
        v[i] = __expf(v[i] - mx);
        sum += v[i];
    }
    __syncthreads();
#pragma unroll
    for (int o = 16; o; o >>= 1) sum += __shfl_xor_sync(0xffffffffu, sum, o);
    if ((tid & 31) == 0) red[tid >> 5] = sum;
    __syncthreads();
    sum = red[0];
#pragma unroll
    for (int i = 1; i < 8; i++) sum += red[i];

    const float inv = 1.0f / sum;
#pragma unroll
    for (int i = 0; i < 8; i++) row[tid + i * 256] = v[i] * inv;
}

// ---------------------------------------------------------------------------
extern "C" void kernel_launch(void* const* d_in, const int* in_sizes, int n_in,
                              void* d_out, int out_size)
{
    (void)in_sizes; (void)n_in; (void)out_size;

    const float* image = (const float*)d_in[0];
    const float* meta  = (const float*)d_in[1];
    const float* Wq_m  = (const float*)d_in[2];  const float* bq_m = (const float*)d_in[3];
    const float* Wk_i  = (const float*)d_in[4];  const float* bk_i = (const float*)d_in[5];
    const float* Wv_i  = (const float*)d_in[6];  const float* bv_i = (const float*)d_in[7];
    const float* Wq_i  = (const float*)d_in[8];  const float* bq_i = (const float*)d_in[9];
    const float* Wk_m  = (const float*)d_in[10]; const float* bk_m = (const float*)d_in[11];
    const float* Wv_m  = (const float*)d_in[12]; const float* bv_m = (const float*)d_in[13];
    const float* Wli   = (const float*)d_in[14]; const float* bli  = (const float*)d_in[15];
    const float* Wlm   = (const float*)d_in[16]; const float* blm  = (const float*)d_in[17];
    float* out = (float*)d_out;

    float *qm, *ki, *vi, *qi, *km, *vm, *si, *sm, *ci, *cm;
    cudaGetSymbolAddress((void**)&qm, g_qm);
    cudaGetSymbolAddress((void**)&ki, g_ki);
    cudaGetSymbolAddress((void**)&vi, g_vi);
    cudaGetSymbolAddress((void**)&qi, g_qi);
    cudaGetSymbolAddress((void**)&km, g_km);
    cudaGetSymbolAddress((void**)&vm, g_vm);
    cudaGetSymbolAddress((void**)&si, g_si);
    cudaGetSymbolAddress((void**)&sm, g_sm);
    cudaGetSymbolAddress((void**)&ci, g_ci);
    cudaGetSymbolAddress((void**)&cm, g_cm);

    const dim3 blk(256);
    const size_t sW = (size_t)DIM * DIM;
    const size_t sO = (size_t)NTOK * DIM;
    const size_t sS = (size_t)NTOK * NTOK;

    // ---- projections: X[2048,512] @ W[h]^T + b[h] -> [H,2048,512]
    const dim3 gproj(DIM / 128, NTOK / 128, NH);
    gemm_mma<<<gproj, blk>>>(meta,  Wq_m, qm, bq_m, nullptr, DIM, DIM, DIM, DIM, 0, 0, 0, sW, sO, DIM);
    gemm_mma<<<gproj, blk>>>(image, Wk_i, ki, bk_i, nullptr, DIM, DIM, DIM, DIM, 0, 0, 0, sW, sO, DIM);
    gemm_mma<<<gproj, blk>>>(image, Wv_i, vi, bv_i, nullptr, DIM, DIM, DIM, DIM, 0, 0, 0, sW, sO, DIM);
    gemm_mma<<<gproj, blk>>>(image, Wq_i, qi, bq_i, nullptr, DIM, DIM, DIM, DIM, 0, 0, 0, sW, sO, DIM);
    gemm_mma<<<gproj, blk>>>(meta,  Wk_m, km, bk_m, nullptr, DIM, DIM, DIM, DIM, 0, 0, 0, sW, sO, DIM);
    gemm_mma<<<gproj, blk>>>(meta,  Wv_m, vm, bv_m, nullptr, DIM, DIM, DIM, DIM, 0, 0, 0, sW, sO, DIM);

    // ---- scores: Q[h] @ K[h]^T -> [H,2048,2048]
    const dim3 gsc(NTOK / 128, NTOK / 128, NH);
    gemm_mma<<<gsc, blk>>>(qm, ki, si, nullptr, nullptr, DIM, DIM, DIM, NTOK, 0, 0, sO, sO, sS, 0);
    gemm_mma<<<gsc, blk>>>(qi, km, sm, nullptr, nullptr, DIM, DIM, DIM, NTOK, 0, 0, sO, sO, sS, 0);

    // ---- softmax rows (scale = 1/sqrt(512))
    const float scale = 0.04419417382415922f;
    softmax_k<<<NH * NTOK, 256>>>(si, scale);
    softmax_k<<<NH * NTOK, 256>>>(sm, scale);

    // ---- AV: P[h] @ V[h]  (B given [k][n] -> bTransB=1) -> concat [2048, H*512]
    const dim3 gav(DIM / 128, NTOK / 128, NH);
    gemm_mma<<<gav, blk>>>(si, vi, ci, nullptr, nullptr, NTOK, NTOK, DIM, NH * DIM, 0, 1, sS, sO, (size_t)DIM, 0);
    gemm_mma<<<gav, blk>>>(sm, vm, cm, nullptr, nullptr, NTOK, NTOK, DIM, NH * DIM, 0, 1, sS, sO, (size_t)DIM, 0);

    // ---- final linears + bias + residual into d_out [2048, 1024]
    const dim3 gfin(DIM / 128, NTOK / 128, 1);
    gemm_mma<<<gfin, blk>>>(ci, Wli, out,       bli, image, NH * DIM, NH * DIM, NH * DIM, 2 * DIM, DIM, 0, 0, 0, 0, 0);
    gemm_mma<<<gfin, blk>>>(cm, Wlm, out + DIM, blm, meta,  NH * DIM, NH * DIM, NH * DIM, 2 * DIM, DIM, 0, 0, 0, 0, 0);
}

// round 6
// speedup vs baseline: 3.4257x; 1.5665x over previous
#include <cuda_runtime.h>
#include <cuda_bf16.h>
#include <cstdint>

static constexpr int NTOK = 2048;
static constexpr int DIM  = 512;
static constexpr int NH   = 8;

// ---------------- scratch (allocation-free: __device__ globals) ----------------
__device__ __align__(128) __nv_bfloat16 g_qm [(size_t)NH * NTOK * DIM];
__device__ __align__(128) __nv_bfloat16 g_ki [(size_t)NH * NTOK * DIM];
__device__ __align__(128) __nv_bfloat16 g_vit[(size_t)NH * DIM * NTOK];  // V_i^T : [h][e][n]
__device__ __align__(128) __nv_bfloat16 g_qi [(size_t)NH * NTOK * DIM];
__device__ __align__(128) __nv_bfloat16 g_km [(size_t)NH * NTOK * DIM];
__device__ __align__(128) __nv_bfloat16 g_vmt[(size_t)NH * DIM * NTOK];  // V_m^T
__device__ __align__(128) float         g_si [(size_t)NH * NTOK * NTOK]; // raw scores fp32
__device__ __align__(128) float         g_sm [(size_t)NH * NTOK * NTOK];
__device__ __align__(128) __nv_bfloat16 g_pi [(size_t)NH * NTOK * NTOK]; // softmax probs bf16
__device__ __align__(128) __nv_bfloat16 g_pm [(size_t)NH * NTOK * NTOK];
__device__ __align__(128) __nv_bfloat16 g_ci [(size_t)NTOK * NH * DIM];  // concat heads bf16
__device__ __align__(128) __nv_bfloat16 g_cm [(size_t)NTOK * NH * DIM];

#define DEVINL __device__ __forceinline__

DEVINL uint32_t s2u(const void* p) { return (uint32_t)__cvta_generic_to_shared(p); }

DEVINL void ldsm4(uint32_t* r, uint32_t a) {
    asm volatile("ldmatrix.sync.aligned.m8n8.x4.shared.b16 {%0,%1,%2,%3}, [%4];"
        : "=r"(r[0]), "=r"(r[1]), "=r"(r[2]), "=r"(r[3]) : "r"(a));
}
DEVINL void mma16(float* c, const uint32_t* a, uint32_t b0, uint32_t b1) {
    asm volatile("mma.sync.aligned.m16n8k16.row.col.f32.bf16.bf16.f32 "
        "{%0,%1,%2,%3},{%4,%5,%6,%7},{%8,%9},{%0,%1,%2,%3};"
        : "+f"(c[0]), "+f"(c[1]), "+f"(c[2]), "+f"(c[3])
        : "r"(a[0]), "r"(a[1]), "r"(a[2]), "r"(a[3]), "r"(b0), "r"(b1));
}
DEVINL uint32_t pk2(float lo, float hi) {
    __nv_bfloat162 t = __floats2bfloat162_rn(lo, hi);
    return *reinterpret_cast<uint32_t*>(&t);
}

static constexpr int RP  = 40;   // smem tile row pitch (bf16): 32 data + 8 pad
static constexpr int RPB = 80;   // bytes
static constexpr int SP  = 132;  // epilogue stage pitch (floats) — MUST be mult of 4
                                 // (R4/R5 crash: pitch 133 broke float2/float4 alignment)

union SmemU {
    __nv_bfloat16 tiles[2][2][128 * RP];  // [buf][A/B]  40960 B
    float stage[64 * SP];                 // epilogue    33792 B
};

// ---------------------------------------------------------------------------
// bf16 mma GEMM (NT):  C[m,n] = sum_k A[m,k] * B[n,k]  (+bias[n]) (+resid)
//   AB/BB: source dtype is bf16 (1) or fp32 (0); fp32 converted on fill.
//   outMode: 0 = fp32 out, 1 = bf16 out, 2 = bf16 out transposed C[n][m].
// CTA 128x128, 256 thr, warp tile 64x32, K-chunk 32, double-buffered smem.
// ---------------------------------------------------------------------------
template <int AB, int BB>
__global__ __launch_bounds__(256, 2) void gemm_bf(
    const void* __restrict__ Av, const void* __restrict__ Bv, void* __restrict__ Cv,
    const float* __restrict__ bias, const float* __restrict__ resid,
    int K, int lda, int ldb, int ldc, int ldr, int outMode,
    size_t strA, size_t strB, size_t strC, size_t strBias)
{
    __shared__ SmemU su;

    const int tid  = threadIdx.x;
    const int warp = tid >> 5, lane = tid & 31;
    const int wm = warp & 1, wn = warp >> 1;
    const int gid = lane >> 2, tig = lane & 3;
    const int z  = blockIdx.z;
    const int m0 = blockIdx.y * 128, n0 = blockIdx.x * 128;

    const char* Ap8 = (const char*)Av + (size_t)z * strA * (AB ? 2 : 4);
    const char* Bp8 = (const char*)Bv + (size_t)z * strB * (BB ? 2 : 4);
    char*       Cp8 = (char*)Cv + (size_t)z * strC * (outMode == 0 ? 4 : 2);
    if (bias) bias += (size_t)z * strBias;

    // fill mapping: row = tid&127, half = tid>>7 (k 0-15 / 16-31)
    const int frow = tid & 127;
    const int fh   = tid >> 7;

    float acc[4][4][4];
#pragma unroll
    for (int i = 0; i < 4; i++)
#pragma unroll
        for (int j = 0; j < 4; j++)
#pragma unroll
            for (int r = 0; r < 4; r++) acc[i][j][r] = 0.0f;

    uint4 qa0, qa1, qb0, qb1;

    auto loadc = [&](int c) {
        const int k0 = c * 32 + fh * 16;
        if (AB) {
            const __nv_bfloat16* p = (const __nv_bfloat16*)Ap8 + (size_t)(m0 + frow) * lda + k0;
            qa0 = *(const uint4*)p; qa1 = *(const uint4*)(p + 8);
        } else {
            const float* p = (const float*)Ap8 + (size_t)(m0 + frow) * lda + k0;
            float4 v0 = *(const float4*)p,     v1 = *(const float4*)(p + 4);
            float4 v2 = *(const float4*)(p + 8), v3 = *(const float4*)(p + 12);
            qa0 = make_uint4(pk2(v0.x, v0.y), pk2(v0.z, v0.w), pk2(v1.x, v1.y), pk2(v1.z, v1.w));
            qa1 = make_uint4(pk2(v2.x, v2.y), pk2(v2.z, v2.w), pk2(v3.x, v3.y), pk2(v3.z, v3.w));
        }
        if (BB) {
            const __nv_bfloat16* p = (const __nv_bfloat16*)Bp8 + (size_t)(n0 + frow) * ldb + k0;
            qb0 = *(const uint4*)p; qb1 = *(const uint4*)(p + 8);
        } else {
            const float* p = (const float*)Bp8 + (size_t)(n0 + frow) * ldb + k0;
            float4 v0 = *(const float4*)p,     v1 = *(const float4*)(p + 4);
            float4 v2 = *(const float4*)(p + 8), v3 = *(const float4*)(p + 12);
            qb0 = make_uint4(pk2(v0.x, v0.y), pk2(v0.z, v0.w), pk2(v1.x, v1.y), pk2(v1.z, v1.w));
            qb1 = make_uint4(pk2(v2.x, v2.y), pk2(v2.z, v2.w), pk2(v3.x, v3.y), pk2(v3.z, v3.w));
        }
    };
    auto storec = [&](int b) {
        __nv_bfloat16* da = &su.tiles[b][0][frow * RP + fh * 16];
        __nv_bfloat16* db = &su.tiles[b][1][frow * RP + fh * 16];
        *(uint4*)da = qa0; *(uint4*)(da + 8) = qa1;
        *(uint4*)db = qb0; *(uint4*)(db + 8) = qb1;
    };

    // ldmatrix per-lane byte offsets
    const int lrow8  = (lane & 7) + ((lane >> 3) & 1) * 8;
    const int lchunk = (lane >> 4) * 16;
    uint32_t aoff[4], boff[2];
#pragma unroll
    for (int mt = 0; mt < 4; mt++) aoff[mt] = (uint32_t)((wm * 64 + mt * 16 + lrow8) * RPB + lchunk);
#pragma unroll
    for (int np = 0; np < 2; np++) boff[np] = (uint32_t)((wn * 32 + np * 16 + lrow8) * RPB + lchunk);

    const int NC = K / 32;
    loadc(0); storec(0);
    __syncthreads();

    for (int c = 0; c < NC; c++) {
        if (c + 1 < NC) loadc(c + 1);
        const uint32_t ab = s2u(&su.tiles[c & 1][0][0]);
        const uint32_t bb = s2u(&su.tiles[c & 1][1][0]);
#pragma unroll
        for (int ks = 0; ks < 2; ks++) {
            uint32_t a[4][4], b[2][4];
#pragma unroll
            for (int mt = 0; mt < 4; mt++) ldsm4(a[mt], ab + aoff[mt] + ks * 32);
#pragma unroll
            for (int np = 0; np < 2; np++) ldsm4(b[np], bb + boff[np] + ks * 32);
#pragma unroll
            for (int mt = 0; mt < 4; mt++)
#pragma unroll
                for (int np = 0; np < 2; np++) {
                    mma16(acc[mt][2 * np],     a[mt], b[np][0], b[np][2]);
                    mma16(acc[mt][2 * np + 1], a[mt], b[np][1], b[np][3]);
                }
        }
        if (c + 1 < NC) storec((c + 1) & 1);
        __syncthreads();
    }

    // -------- epilogue: stage 64 m-rows at a time --------
    for (int p = 0; p < 2; p++) {
        if (wm == p) {
#pragma unroll
            for (int mt = 0; mt < 4; mt++) {
                const int lr = mt * 16 + gid;
#pragma unroll
                for (int nt = 0; nt < 4; nt++) {
                    const int col = wn * 32 + nt * 8 + 2 * tig;
                    *(float2*)&su.stage[lr * SP + col]       = make_float2(acc[mt][nt][0], acc[mt][nt][1]);
                    *(float2*)&su.stage[(lr + 8) * SP + col] = make_float2(acc[mt][nt][2], acc[mt][nt][3]);
                }
            }
        }
        __syncthreads();

        if (outMode == 0) {
            float* C = (float*)Cp8;
#pragma unroll
            for (int i = 0; i < 8; i++) {
                const int idx = tid + i * 256;
                const int row = idx >> 5;
                const int c4  = (idx & 31) * 4;
                float4 v = *(float4*)&su.stage[row * SP + c4];
                const int n = n0 + c4;
                if (bias) { v.x += bias[n]; v.y += bias[n + 1]; v.z += bias[n + 2]; v.w += bias[n + 3]; }
                const int m = m0 + p * 64 + row;
                if (resid) {
                    float4 rr = *(const float4*)(resid + (size_t)m * ldr + n);
                    v.x += rr.x; v.y += rr.y; v.z += rr.z; v.w += rr.w;
                }
                *(float4*)(C + (size_t)m * ldc + n) = v;
            }
        } else if (outMode == 1) {
            __nv_bfloat16* C = (__nv_bfloat16*)Cp8;
#pragma unroll
            for (int i = 0; i < 8; i++) {
                const int idx = tid + i * 256;
                const int row = idx >> 5;
                const int c4  = (idx & 31) * 4;
                float4 v = *(float4*)&su.stage[row * SP + c4];
                const int n = n0 + c4;
                if (bias) { v.x += bias[n]; v.y += bias[n + 1]; v.z += bias[n + 2]; v.w += bias[n + 3]; }
                uint2 o = make_uint2(pk2(v.x, v.y), pk2(v.z, v.w));
                *(uint2*)(C + (size_t)(m0 + p * 64 + row) * ldc + n) = o;
            }
        } else {
            // transposed bf16: C[n][m]  (scalar smem reads; pitch-132 conflicts OK)
            __nv_bfloat16* C = (__nv_bfloat16*)Cp8;
#pragma unroll
            for (int i = 0; i < 8; i++) {
                const int idx = tid + i * 256;
                const int mq  = (idx & 15) * 4;
                const int col = idx >> 4;
                const float bv = bias ? bias[n0 + col] : 0.0f;
                float f0 = su.stage[(mq + 0) * SP + col] + bv;
                float f1 = su.stage[(mq + 1) * SP + col] + bv;
                float f2 = su.stage[(mq + 2) * SP + col] + bv;
                float f3 = su.stage[(mq + 3) * SP + col] + bv;
                uint2 o = make_uint2(pk2(f0, f1), pk2(f2, f3));
                *(uint2*)(C + (size_t)(n0 + col) * ldc + m0 + p * 64 + mq) = o;
            }
        }
        __syncthreads();
    }
}

// ---------------------------------------------------------------------------
// Row softmax (2048 cols): fp32 in -> bf16 probs out, one block per row.
// ---------------------------------------------------------------------------
__global__ __launch_bounds__(256) void softmax_bf(
    const float* __restrict__ S, __nv_bfloat16* __restrict__ P, float scale)
{
    const float* row = S + (size_t)blockIdx.x * NTOK;
    __nv_bfloat16* prow = P + (size_t)blockIdx.x * NTOK;
    const int tid = threadIdx.x;

    float4 u0 = *(const float4*)(row + tid * 8);
    float4 u1 = *(const float4*)(row + tid * 8 + 4);
    float v[8] = {u0.x, u0.y, u0.z, u0.w, u1.x, u1.y, u1.z, u1.w};

    float mx = -1e30f;
#pragma unroll
    for (int i = 0; i < 8; i++) { v[i] *= scale; mx = fmaxf(mx, v[i]); }

    __shared__ float red[8];
#pragma unroll
    for (int o = 16; o; o >>= 1) mx = fmaxf(mx, __shfl_xor_sync(0xffffffffu, mx, o));
    if ((tid & 31) == 0) red[tid >> 5] = mx;
    __syncthreads();
    mx = red[0];
#pragma unroll
    for (int i = 1; i < 8; i++) mx = fmaxf(mx, red[i]);

    float sum = 0.0f;
#pragma unroll
    for (int i = 0; i < 8; i++) { v[i] = __expf(v[i] - mx); sum += v[i]; }
    __syncthreads();
#pragma unroll
    for (int o = 16; o; o >>= 1) sum += __shfl_xor_sync(0xffffffffu, sum, o);
    if ((tid & 31) == 0) red[tid >> 5] = sum;
    __syncthreads();
    sum = red[0];
#pragma unroll
    for (int i = 1; i < 8; i++) sum += red[i];

    const float inv = 1.0f / sum;
    uint4 o = make_uint4(pk2(v[0] * inv, v[1] * inv), pk2(v[2] * inv, v[3] * inv),
                         pk2(v[4] * inv, v[5] * inv), pk2(v[6] * inv, v[7] * inv));
    *(uint4*)(prow + tid * 8) = o;
}

// ---------------------------------------------------------------------------
extern "C" void kernel_launch(void* const* d_in, const int* in_sizes, int n_in,
                              void* d_out, int out_size)
{
    (void)in_sizes; (void)n_in; (void)out_size;

    const float* image = (const float*)d_in[0];
    const float* meta  = (const float*)d_in[1];
    const float* Wq_m  = (const float*)d_in[2];  const float* bq_m = (const float*)d_in[3];
    const float* Wk_i  = (const float*)d_in[4];  const float* bk_i = (const float*)d_in[5];
    const float* Wv_i  = (const float*)d_in[6];  const float* bv_i = (const float*)d_in[7];
    const float* Wq_i  = (const float*)d_in[8];  const float* bq_i = (const float*)d_in[9];
    const float* Wk_m  = (const float*)d_in[10]; const float* bk_m = (const float*)d_in[11];
    const float* Wv_m  = (const float*)d_in[12]; const float* bv_m = (const float*)d_in[13];
    const float* Wli   = (const float*)d_in[14]; const float* bli  = (const float*)d_in[15];
    const float* Wlm   = (const float*)d_in[16]; const float* blm  = (const float*)d_in[17];
    float* out = (float*)d_out;

    __nv_bfloat16 *qm, *ki, *vit, *qi, *km, *vmt, *pi, *pm, *ci, *cm;
    float *si, *sm;
    cudaGetSymbolAddress((void**)&qm,  g_qm);
    cudaGetSymbolAddress((void**)&ki,  g_ki);
    cudaGetSymbolAddress((void**)&vit, g_vit);
    cudaGetSymbolAddress((void**)&qi,  g_qi);
    cudaGetSymbolAddress((void**)&km,  g_km);
    cudaGetSymbolAddress((void**)&vmt, g_vmt);
    cudaGetSymbolAddress((void**)&si,  g_si);
    cudaGetSymbolAddress((void**)&sm,  g_sm);
    cudaGetSymbolAddress((void**)&pi,  g_pi);
    cudaGetSymbolAddress((void**)&pm,  g_pm);
    cudaGetSymbolAddress((void**)&ci,  g_ci);
    cudaGetSymbolAddress((void**)&cm,  g_cm);

    const dim3 blk(256);
    const size_t sW = (size_t)DIM * DIM;
    const size_t sO = (size_t)NTOK * DIM;   // per-head Q/K stride
    const size_t sS = (size_t)NTOK * NTOK;

    // ---- projections (fp32 x fp32 -> bf16): X @ W[h]^T + b[h]
    const dim3 gproj(DIM / 128, NTOK / 128, NH);
    gemm_bf<0, 0><<<gproj, blk>>>(meta,  Wq_m, qm,  bq_m, nullptr, DIM, DIM, DIM, DIM,  0, 1, 0, sW, sO, DIM);
    gemm_bf<0, 0><<<gproj, blk>>>(image, Wk_i, ki,  bk_i, nullptr, DIM, DIM, DIM, DIM,  0, 1, 0, sW, sO, DIM);
    gemm_bf<0, 0><<<gproj, blk>>>(image, Wv_i, vit, bv_i, nullptr, DIM, DIM, DIM, NTOK, 0, 2, 0, sW, sO, DIM);
    gemm_bf<0, 0><<<gproj, blk>>>(image, Wq_i, qi,  bq_i, nullptr, DIM, DIM, DIM, DIM,  0, 1, 0, sW, sO, DIM);
    gemm_bf<0, 0><<<gproj, blk>>>(meta,  Wk_m, km,  bk_m, nullptr, DIM, DIM, DIM, DIM,  0, 1, 0, sW, sO, DIM);
    gemm_bf<0, 0><<<gproj, blk>>>(meta,  Wv_m, vmt, bv_m, nullptr, DIM, DIM, DIM, NTOK, 0, 2, 0, sW, sO, DIM);

    // ---- scores (bf16 x bf16 -> fp32): Q[h] @ K[h]^T
    const dim3 gsc(NTOK / 128, NTOK / 128, NH);
    gemm_bf<1, 1><<<gsc, blk>>>(qm, ki, si, nullptr, nullptr, DIM, DIM, DIM, NTOK, 0, 0, sO, sO, sS, 0);
    gemm_bf<1, 1><<<gsc, blk>>>(qi, km, sm, nullptr, nullptr, DIM, DIM, DIM, NTOK, 0, 0, sO, sO, sS, 0);

    // ---- softmax (fp32 -> bf16 probs), scale = 1/sqrt(512)
    const float scale = 0.04419417382415922f;
    softmax_bf<<<NH * NTOK, 256>>>(si, pi, scale);
    softmax_bf<<<NH * NTOK, 256>>>(sm, pm, scale);

    // ---- AV (bf16 x bf16 -> bf16): P[h] @ (V^T[h])^T -> concat [2048, H*512]
    const dim3 gav(DIM / 128, NTOK / 128, NH);
    gemm_bf<1, 1><<<gav, blk>>>(pi, vit, ci, nullptr, nullptr, NTOK, NTOK, NTOK, NH * DIM, 0, 1, sS, sO, (size_t)DIM, 0);
    gemm_bf<1, 1><<<gav, blk>>>(pm, vmt, cm, nullptr, nullptr, NTOK, NTOK, NTOK, NH * DIM, 0, 1, sS, sO, (size_t)DIM, 0);

    // ---- final linears (bf16 x fp32 -> fp32) + bias + residual into d_out [2048,1024]
    const dim3 gfin(DIM / 128, NTOK / 128, 1);
    gemm_bf<1, 0><<<gfin, blk>>>(ci, Wli, out,       bli, image, NH * DIM, NH * DIM, NH * DIM, 2 * DIM, DIM, 0, 0, 0, 0, 0);
    gemm_bf<1, 0><<<gfin, blk>>>(cm, Wlm, out + DIM, blm, meta,  NH * DIM, NH * DIM, NH * DIM, 2 * DIM, DIM, 0, 0, 0, 0, 0);
}

// round 7
// speedup vs baseline: 4.8135x; 1.4051x over previous
#include <cuda_runtime.h>
#include <cuda_bf16.h>
#include <cstdint>

static constexpr int NTOK = 2048;
static constexpr int DIM  = 512;
static constexpr int NH   = 8;

// ---------------- scratch (allocation-free: __device__ globals) ----------------
__device__ __align__(128) __nv_bfloat16 g_bimg[(size_t)NTOK * DIM];           // image bf16
__device__ __align__(128) __nv_bfloat16 g_bmet[(size_t)NTOK * DIM];           // meta  bf16
__device__ __align__(128) __nv_bfloat16 g_wqm [(size_t)NH * DIM * DIM];
__device__ __align__(128) __nv_bfloat16 g_wki [(size_t)NH * DIM * DIM];
__device__ __align__(128) __nv_bfloat16 g_wvi [(size_t)NH * DIM * DIM];
__device__ __align__(128) __nv_bfloat16 g_wqi [(size_t)NH * DIM * DIM];
__device__ __align__(128) __nv_bfloat16 g_wkm [(size_t)NH * DIM * DIM];
__device__ __align__(128) __nv_bfloat16 g_wvm [(size_t)NH * DIM * DIM];
__device__ __align__(128) __nv_bfloat16 g_wli [(size_t)DIM * NH * DIM];
__device__ __align__(128) __nv_bfloat16 g_wlm [(size_t)DIM * NH * DIM];
__device__ __align__(128) __nv_bfloat16 g_qm  [(size_t)NH * NTOK * DIM];
__device__ __align__(128) __nv_bfloat16 g_ki  [(size_t)NH * NTOK * DIM];
__device__ __align__(128) __nv_bfloat16 g_vit [(size_t)NH * DIM * NTOK];      // V_i^T
__device__ __align__(128) __nv_bfloat16 g_qi  [(size_t)NH * NTOK * DIM];
__device__ __align__(128) __nv_bfloat16 g_km  [(size_t)NH * NTOK * DIM];
__device__ __align__(128) __nv_bfloat16 g_vmt [(size_t)NH * DIM * NTOK];      // V_m^T
__device__ __align__(128) float         g_si  [(size_t)NH * NTOK * NTOK];
__device__ __align__(128) float         g_sm  [(size_t)NH * NTOK * NTOK];
__device__ __align__(128) __nv_bfloat16 g_pi  [(size_t)NH * NTOK * NTOK];
__device__ __align__(128) __nv_bfloat16 g_pm  [(size_t)NH * NTOK * NTOK];
__device__ __align__(128) __nv_bfloat16 g_ci  [(size_t)NTOK * NH * DIM];
__device__ __align__(128) __nv_bfloat16 g_cm  [(size_t)NTOK * NH * DIM];

#define DEVINL __device__ __forceinline__

DEVINL uint32_t s2u(const void* p) { return (uint32_t)__cvta_generic_to_shared(p); }

DEVINL void ldsm4(uint32_t* r, uint32_t a) {
    asm volatile("ldmatrix.sync.aligned.m8n8.x4.shared.b16 {%0,%1,%2,%3}, [%4];"
        : "=r"(r[0]), "=r"(r[1]), "=r"(r[2]), "=r"(r[3]) : "r"(a));
}
DEVINL void mma16(float* c, const uint32_t* a, uint32_t b0, uint32_t b1) {
    asm volatile("mma.sync.aligned.m16n8k16.row.col.f32.bf16.bf16.f32 "
        "{%0,%1,%2,%3},{%4,%5,%6,%7},{%8,%9},{%0,%1,%2,%3};"
        : "+f"(c[0]), "+f"(c[1]), "+f"(c[2]), "+f"(c[3])
        : "r"(a[0]), "r"(a[1]), "r"(a[2]), "r"(a[3]), "r"(b0), "r"(b1));
}
DEVINL uint32_t pk2(float lo, float hi) {
    __nv_bfloat162 t = __floats2bfloat162_rn(lo, hi);
    return *reinterpret_cast<uint32_t*>(&t);
}
DEVINL void cp16(uint32_t dst, const void* src) {
    asm volatile("cp.async.cg.shared.global [%0], [%1], 16;" :: "r"(dst), "l"(src));
}
#define CP_COMMIT() asm volatile("cp.async.commit_group;")
#define CP_WAIT(n)  asm volatile("cp.async.wait_group %0;" :: "n"(n))

static constexpr int RP   = 40;   // smem tile row pitch (bf16): 32 data + 8 pad
static constexpr int RPB  = 80;   // bytes
static constexpr int SP   = 132;  // epilogue stage pitch (floats) — mult of 4 (R5 lesson)
static constexpr int NS   = 4;    // cp.async pipeline stages
static constexpr int TILE_B  = 128 * RPB;            // 10240 B per tile
static constexpr int STAGE_B = 2 * TILE_B;           // A+B per stage
static constexpr int SMEM_DYN = NS * STAGE_B;        // 81920 B

// ---------------------------------------------------------------------------
// bf16 mma GEMM (NT):  C[m,n] = sum_k A[m,k] * B[n,k]  (+bias[n]) (+resid)
//   outMode: 0 = fp32 out, 1 = bf16 out, 2 = bf16 out transposed C[n][m].
// CTA 128x128, 256 thr, warp tile 64x32, K-chunk 32, 4-stage cp.async.
// ---------------------------------------------------------------------------
__global__ __launch_bounds__(256, 2) void gemm_bf(
    const __nv_bfloat16* __restrict__ A, const __nv_bfloat16* __restrict__ B,
    void* __restrict__ Cv,
    const float* __restrict__ bias, const float* __restrict__ resid,
    int K, int lda, int ldb, int ldc, int ldr, int outMode,
    size_t strA, size_t strB, size_t strC, size_t strBias)
{
    extern __shared__ __align__(128) char dsm[];
    const uint32_t sbase = s2u(dsm);

    const int tid  = threadIdx.x;
    const int warp = tid >> 5, lane = tid & 31;
    const int wm = warp & 1, wn = warp >> 1;
    const int gid = lane >> 2, tig = lane & 3;
    const int z  = blockIdx.z;
    const int m0 = blockIdx.y * 128, n0 = blockIdx.x * 128;

    A += (size_t)z * strA;
    B += (size_t)z * strB;
    char* Cp8 = (char*)Cv + (size_t)z * strC * (outMode == 0 ? 4 : 2);
    if (bias) bias += (size_t)z * strBias;

    // fill mapping: row = tid&127; up = (tid>>7)*2 -> 16B units {up, up+1} of 64B row
    const int frow = tid & 127;
    const int fup  = (tid >> 7) * 2;
    const __nv_bfloat16* Ap = A + (size_t)(m0 + frow) * lda + fup * 8;
    const __nv_bfloat16* Bp = B + (size_t)(n0 + frow) * ldb + fup * 8;
    const uint32_t sa_t = sbase + frow * RPB + fup * 16;
    const uint32_t sb_t = sa_t + TILE_B;

    const int NC = K / 32;

    auto issue = [&](int c) {
        const uint32_t so = (uint32_t)((c & (NS - 1)) * STAGE_B);
        const __nv_bfloat16* ga = Ap + c * 32;
        const __nv_bfloat16* gb = Bp + c * 32;
        cp16(sa_t + so,      ga);
        cp16(sa_t + so + 16, ga + 8);
        cp16(sb_t + so,      gb);
        cp16(sb_t + so + 16, gb + 8);
    };

    float acc[4][4][4];
#pragma unroll
    for (int i = 0; i < 4; i++)
#pragma unroll
        for (int j = 0; j < 4; j++)
#pragma unroll
            for (int r = 0; r < 4; r++) acc[i][j][r] = 0.0f;

    // ldmatrix per-lane byte offsets (within a stage's A/B tile)
    const int lrow8  = (lane & 7) + ((lane >> 3) & 1) * 8;
    const int lchunk = (lane >> 4) * 16;
    uint32_t aoff[4], boff[2];
#pragma unroll
    for (int mt = 0; mt < 4; mt++) aoff[mt] = (uint32_t)((wm * 64 + mt * 16 + lrow8) * RPB + lchunk);
#pragma unroll
    for (int np = 0; np < 2; np++) boff[np] = (uint32_t)((wn * 32 + np * 16 + lrow8) * RPB + lchunk);

    // prologue: stages 0..NS-2
#pragma unroll
    for (int c = 0; c < NS - 1; c++) {
        if (c < NC) issue(c);
        CP_COMMIT();
    }

    for (int c = 0; c < NC; c++) {
        CP_WAIT(NS - 2);
        __syncthreads();
        if (c + NS - 1 < NC) issue(c + NS - 1);
        CP_COMMIT();

        const uint32_t so = (uint32_t)((c & (NS - 1)) * STAGE_B);
        const uint32_t ab = sbase + so;
        const uint32_t bb = ab + TILE_B;
#pragma unroll
        for (int ks = 0; ks < 2; ks++) {
            uint32_t a[4][4], b[2][4];
#pragma unroll
            for (int mt = 0; mt < 4; mt++) ldsm4(a[mt], ab + aoff[mt] + ks * 32);
#pragma unroll
            for (int np = 0; np < 2; np++) ldsm4(b[np], bb + boff[np] + ks * 32);
#pragma unroll
            for (int mt = 0; mt < 4; mt++)
#pragma unroll
                for (int np = 0; np < 2; np++) {
                    mma16(acc[mt][2 * np],     a[mt], b[np][0], b[np][2]);
                    mma16(acc[mt][2 * np + 1], a[mt], b[np][1], b[np][3]);
                }
        }
    }
    CP_WAIT(0);
    __syncthreads();

    // -------- epilogue: stage 64 m-rows at a time through smem --------
    float* stage = (float*)dsm;
    for (int p = 0; p < 2; p++) {
        if (wm == p) {
#pragma unroll
            for (int mt = 0; mt < 4; mt++) {
                const int lr = mt * 16 + gid;
#pragma unroll
                for (int nt = 0; nt < 4; nt++) {
                    const int col = wn * 32 + nt * 8 + 2 * tig;
                    *(float2*)&stage[lr * SP + col]       = make_float2(acc[mt][nt][0], acc[mt][nt][1]);
                    *(float2*)&stage[(lr + 8) * SP + col] = make_float2(acc[mt][nt][2], acc[mt][nt][3]);
                }
            }
        }
        __syncthreads();

        if (outMode == 0) {
            float* C = (float*)Cp8;
#pragma unroll
            for (int i = 0; i < 8; i++) {
                const int idx = tid + i * 256;
                const int row = idx >> 5;
                const int c4  = (idx & 31) * 4;
                float4 v = *(float4*)&stage[row * SP + c4];
                const int n = n0 + c4;
                if (bias) { v.x += bias[n]; v.y += bias[n + 1]; v.z += bias[n + 2]; v.w += bias[n + 3]; }
                const int m = m0 + p * 64 + row;
                if (resid) {
                    float4 rr = *(const float4*)(resid + (size_t)m * ldr + n);
                    v.x += rr.x; v.y += rr.y; v.z += rr.z; v.w += rr.w;
                }
                *(float4*)(C + (size_t)m * ldc + n) = v;
            }
        } else if (outMode == 1) {
            __nv_bfloat16* C = (__nv_bfloat16*)Cp8;
#pragma unroll
            for (int i = 0; i < 8; i++) {
                const int idx = tid + i * 256;
                const int row = idx >> 5;
                const int c4  = (idx & 31) * 4;
                float4 v = *(float4*)&stage[row * SP + c4];
                const int n = n0 + c4;
                if (bias) { v.x += bias[n]; v.y += bias[n + 1]; v.z += bias[n + 2]; v.w += bias[n + 3]; }
                uint2 o = make_uint2(pk2(v.x, v.y), pk2(v.z, v.w));
                *(uint2*)(C + (size_t)(m0 + p * 64 + row) * ldc + n) = o;
            }
        } else {
            __nv_bfloat16* C = (__nv_bfloat16*)Cp8;
#pragma unroll
            for (int i = 0; i < 8; i++) {
                const int idx = tid + i * 256;
                const int mq  = (idx & 15) * 4;
                const int col = idx >> 4;
                const float bv = bias ? bias[n0 + col] : 0.0f;
                float f0 = stage[(mq + 0) * SP + col] + bv;
                float f1 = stage[(mq + 1) * SP + col] + bv;
                float f2 = stage[(mq + 2) * SP + col] + bv;
                float f3 = stage[(mq + 3) * SP + col] + bv;
                uint2 o = make_uint2(pk2(f0, f1), pk2(f2, f3));
                *(uint2*)(C + (size_t)(n0 + col) * ldc + m0 + p * 64 + mq) = o;
            }
        }
        __syncthreads();
    }
}

// ---------------------------------------------------------------------------
// fp32 -> bf16 bulk convert, 10 tensors in one launch (grid.y = tensor idx)
// ---------------------------------------------------------------------------
struct CvtJobs { const float* s[10]; __nv_bfloat16* d[10]; int n[10]; };

__global__ __launch_bounds__(256) void cvt_bf(CvtJobs j)
{
    const int t = blockIdx.y;
    const float* src = j.s[t];
    __nv_bfloat16* dst = j.d[t];
    const int n = j.n[t];
    const int stride = gridDim.x * blockDim.x * 4;
    for (int i = (blockIdx.x * blockDim.x + threadIdx.x) * 4; i < n; i += stride) {
        float4 v = *(const float4*)(src + i);
        uint2 o = make_uint2(pk2(v.x, v.y), pk2(v.z, v.w));
        *(uint2*)(dst + i) = o;
    }
}

// ---------------------------------------------------------------------------
// Row softmax (2048 cols): fp32 in -> bf16 probs out, one block per row.
// ---------------------------------------------------------------------------
__global__ __launch_bounds__(256) void softmax_bf(
    const float* __restrict__ S, __nv_bfloat16* __restrict__ P, float scale)
{
    const float* row = S + (size_t)blockIdx.x * NTOK;
    __nv_bfloat16* prow = P + (size_t)blockIdx.x * NTOK;
    const int tid = threadIdx.x;

    float4 u0 = *(const float4*)(row + tid * 8);
    float4 u1 = *(const float4*)(row + tid * 8 + 4);
    float v[8] = {u0.x, u0.y, u0.z, u0.w, u1.x, u1.y, u1.z, u1.w};

    float mx = -1e30f;
#pragma unroll
    for (int i = 0; i < 8; i++) { v[i] *= scale; mx = fmaxf(mx, v[i]); }

    __shared__ float red[8];
#pragma unroll
    for (int o = 16; o; o >>= 1) mx = fmaxf(mx, __shfl_xor_sync(0xffffffffu, mx, o));
    if ((tid & 31) == 0) red[tid >> 5] = mx;
    __syncthreads();
    mx = red[0];
#pragma unroll
    for (int i = 1; i < 8; i++) mx = fmaxf(mx, red[i]);

    float sum = 0.0f;
#pragma unroll
    for (int i = 0; i < 8; i++) { v[i] = __expf(v[i] - mx); sum += v[i]; }
    __syncthreads();
#pragma unroll
    for (int o = 16; o; o >>= 1) sum += __shfl_xor_sync(0xffffffffu, sum, o);
    if ((tid & 31) == 0) red[tid >> 5] = sum;
    __syncthreads();
    sum = red[0];
#pragma unroll
    for (int i = 1; i < 8; i++) sum += red[i];

    const float inv = 1.0f / sum;
    uint4 o = make_uint4(pk2(v[0] * inv, v[1] * inv), pk2(v[2] * inv, v[3] * inv),
                         pk2(v[4] * inv, v[5] * inv), pk2(v[6] * inv, v[7] * inv));
    *(uint4*)(prow + tid * 8) = o;
}

// ---------------------------------------------------------------------------
extern "C" void kernel_launch(void* const* d_in, const int* in_sizes, int n_in,
                              void* d_out, int out_size)
{
    (void)in_sizes; (void)n_in; (void)out_size;

    const float* image = (const float*)d_in[0];
    const float* meta  = (const float*)d_in[1];
    const float* Wq_m  = (const float*)d_in[2];  const float* bq_m = (const float*)d_in[3];
    const float* Wk_i  = (const float*)d_in[4];  const float* bk_i = (const float*)d_in[5];
    const float* Wv_i  = (const float*)d_in[6];  const float* bv_i = (const float*)d_in[7];
    const float* Wq_i  = (const float*)d_in[8];  const float* bq_i = (const float*)d_in[9];
    const float* Wk_m  = (const float*)d_in[10]; const float* bk_m = (const float*)d_in[11];
    const float* Wv_m  = (const float*)d_in[12]; const float* bv_m = (const float*)d_in[13];
    const float* Wli   = (const float*)d_in[14]; const float* bli  = (const float*)d_in[15];
    const float* Wlm   = (const float*)d_in[16]; const float* blm  = (const float*)d_in[17];
    float* out = (float*)d_out;

    __nv_bfloat16 *bimg, *bmet, *wqm, *wki, *wvi, *wqi, *wkm, *wvm, *wli, *wlm;
    __nv_bfloat16 *qm, *ki, *vit, *qi, *km, *vmt, *pi, *pm, *ci, *cm;
    float *si, *sm;
    cudaGetSymbolAddress((void**)&bimg, g_bimg);
    cudaGetSymbolAddress((void**)&bmet, g_bmet);
    cudaGetSymbolAddress((void**)&wqm,  g_wqm);
    cudaGetSymbolAddress((void**)&wki,  g_wki);
    cudaGetSymbolAddress((void**)&wvi,  g_wvi);
    cudaGetSymbolAddress((void**)&wqi,  g_wqi);
    cudaGetSymbolAddress((void**)&wkm,  g_wkm);
    cudaGetSymbolAddress((void**)&wvm,  g_wvm);
    cudaGetSymbolAddress((void**)&wli,  g_wli);
    cudaGetSymbolAddress((void**)&wlm,  g_wlm);
    cudaGetSymbolAddress((void**)&qm,   g_qm);
    cudaGetSymbolAddress((void**)&ki,   g_ki);
    cudaGetSymbolAddress((void**)&vit,  g_vit);
    cudaGetSymbolAddress((void**)&qi,   g_qi);
    cudaGetSymbolAddress((void**)&km,   g_km);
    cudaGetSymbolAddress((void**)&vmt,  g_vmt);
    cudaGetSymbolAddress((void**)&si,   g_si);
    cudaGetSymbolAddress((void**)&sm,   g_sm);
    cudaGetSymbolAddress((void**)&pi,   g_pi);
    cudaGetSymbolAddress((void**)&pm,   g_pm);
    cudaGetSymbolAddress((void**)&ci,   g_ci);
    cudaGetSymbolAddress((void**)&cm,   g_cm);

    cudaFuncSetAttribute(gemm_bf, cudaFuncAttributeMaxDynamicSharedMemorySize, SMEM_DYN);

    // ---- pre-convert all fp32 operands to bf16 (one launch)
    {
        CvtJobs j;
        const int nW = NH * DIM * DIM;          // 2M
        const int nL = DIM * NH * DIM;          // 2M
        const int nX = NTOK * DIM;              // 1M
        j.s[0] = image; j.d[0] = bimg; j.n[0] = nX;
        j.s[1] = meta;  j.d[1] = bmet; j.n[1] = nX;
        j.s[2] = Wq_m;  j.d[2] = wqm;  j.n[2] = nW;
        j.s[3] = Wk_i;  j.d[3] = wki;  j.n[3] = nW;
        j.s[4] = Wv_i;  j.d[4] = wvi;  j.n[4] = nW;
        j.s[5] = Wq_i;  j.d[5] = wqi;  j.n[5] = nW;
        j.s[6] = Wk_m;  j.d[6] = wkm;  j.n[6] = nW;
        j.s[7] = Wv_m;  j.d[7] = wvm;  j.n[7] = nW;
        j.s[8] = Wli;   j.d[8] = wli;  j.n[8] = nL;
        j.s[9] = Wlm;   j.d[9] = wlm;  j.n[9] = nL;
        cvt_bf<<<dim3(1024, 10), 256>>>(j);
    }

    const dim3 blk(256);
    const size_t sW = (size_t)DIM * DIM;
    const size_t sO = (size_t)NTOK * DIM;
    const size_t sS = (size_t)NTOK * NTOK;

    // ---- projections (bf16): X @ W[h]^T + b[h]
    const dim3 gproj(DIM / 128, NTOK / 128, NH);
    gemm_bf<<<gproj, blk, SMEM_DYN>>>(bmet, wqm, qm,  bq_m, nullptr, DIM, DIM, DIM, DIM,  0, 1, 0, sW, sO, DIM);
    gemm_bf<<<gproj, blk, SMEM_DYN>>>(bimg, wki, ki,  bk_i, nullptr, DIM, DIM, DIM, DIM,  0, 1, 0, sW, sO, DIM);
    gemm_bf<<<gproj, blk, SMEM_DYN>>>(bimg, wvi, vit, bv_i, nullptr, DIM, DIM, DIM, NTOK, 0, 2, 0, sW, sO, DIM);
    gemm_bf<<<gproj, blk, SMEM_DYN>>>(bimg, wqi, qi,  bq_i, nullptr, DIM, DIM, DIM, DIM,  0, 1, 0, sW, sO, DIM);
    gemm_bf<<<gproj, blk, SMEM_DYN>>>(bmet, wkm, km,  bk_m, nullptr, DIM, DIM, DIM, DIM,  0, 1, 0, sW, sO, DIM);
    gemm_bf<<<gproj, blk, SMEM_DYN>>>(bmet, wvm, vmt, bv_m, nullptr, DIM, DIM, DIM, NTOK, 0, 2, 0, sW, sO, DIM);

    // ---- scores: Q[h] @ K[h]^T -> fp32
    const dim3 gsc(NTOK / 128, NTOK / 128, NH);
    gemm_bf<<<gsc, blk, SMEM_DYN>>>(qm, ki, si, nullptr, nullptr, DIM, DIM, DIM, NTOK, 0, 0, sO, sO, sS, 0);
    gemm_bf<<<gsc, blk, SMEM_DYN>>>(qi, km, sm, nullptr, nullptr, DIM, DIM, DIM, NTOK, 0, 0, sO, sO, sS, 0);

    // ---- softmax (fp32 -> bf16), scale = 1/sqrt(512)
    const float scale = 0.04419417382415922f;
    softmax_bf<<<NH * NTOK, 256>>>(si, pi, scale);
    softmax_bf<<<NH * NTOK, 256>>>(sm, pm, scale);

    // ---- AV: P[h] @ (V^T[h])^T -> concat [2048, H*512] bf16
    const dim3 gav(DIM / 128, NTOK / 128, NH);
    gemm_bf<<<gav, blk, SMEM_DYN>>>(pi, vit, ci, nullptr, nullptr, NTOK, NTOK, NTOK, NH * DIM, 0, 1, sS, sO, (size_t)DIM, 0);
    gemm_bf<<<gav, blk, SMEM_DYN>>>(pm, vmt, cm, nullptr, nullptr, NTOK, NTOK, NTOK, NH * DIM, 0, 1, sS, sO, (size_t)DIM, 0);

    // ---- final linears + bias + residual(fp32) into d_out [2048, 1024]
    const dim3 gfin(DIM / 128, NTOK / 128, 1);
    gemm_bf<<<gfin, blk, SMEM_DYN>>>(ci, wli, out,       bli, image, NH * DIM, NH * DIM, NH * DIM, 2 * DIM, DIM, 0, 0, 0, 0, 0);
    gemm_bf<<<gfin, blk, SMEM_DYN>>>(cm, wlm, out + DIM, blm, meta,  NH * DIM, NH * DIM, NH * DIM, 2 * DIM, DIM, 0, 0, 0, 0, 0);
}